// round 10
// baseline (speedup 1.0000x reference)
#include <cuda_runtime.h>
#include <math.h>

#define NCTA 128
#define NTH  256
#define HDIM 512
#define BD   128
#define TENC 512
#define PRED 32
#define JPC  4   // hidden units per CTA

typedef unsigned long long ull;

// ---------------- device scratch (static, no allocation) ----------------
__device__ float g_h[2][HDIM * BD];                      // ping-pong hidden [j][b]
__device__ float g_enc[(size_t)TENC * HDIM * BD];        // encoder outputs [t][j][b] fp32 (134MB)
__device__ float g_p[TENC * BD];                         // p[t][b] = enc_t[b] . lin_W
__device__ float g_sc[TENC * BD];                        // attention scores [t][b]
__device__ float g_x[BD];                                // decoder input x[b]
__device__ volatile unsigned g_gen = 0;
__device__ unsigned g_cnt = 0;

// ---------------- helpers ----------------
__device__ __forceinline__ void fma2(ull& d, ull a, ull b) {
    asm("fma.rn.f32x2 %0, %1, %2, %0;" : "+l"(d) : "l"(a), "l"(b));
}
__device__ __forceinline__ ull pk(float a, float b) {
    ull r; asm("mov.b64 %0, {%1, %2};" : "=l"(r) : "f"(a), "f"(b)); return r;
}
__device__ __forceinline__ float2 upk(ull v) {
    float2 r; asm("mov.b64 {%0, %1}, %2;" : "=f"(r.x), "=f"(r.y) : "l"(v)); return r;
}
__device__ __forceinline__ float sigf(float x) { return 1.0f / (1.0f + expf(-x)); }

// Software grid barrier: 128 CTAs, 1/SM, all co-resident. Generation-based,
// re-entrant across graph replays (equality test => wraparound harmless).
__device__ __forceinline__ void grid_sync() {
    __syncthreads();
    if (threadIdx.x == 0) {
        __threadfence();
        unsigned gen = g_gen;
        if (atomicAdd(&g_cnt, 1u) == NCTA - 1u) {
            g_cnt = 0u;
            __threadfence();
            g_gen = gen + 1u;
        } else {
            while (g_gen == gen) { __nanosleep(40); }
        }
        __threadfence();
    }
    __syncthreads();
}

// SMEM layout (dynamic, 77952 B):
//   Wd     : ull[16][512]   65536 B   (w,w)-duplicated weight rows
//   gsm    : float[2048]     8192 B   gate staging / linW / reduce2
//   c_s    : float[512]      2048 B   cell state
//   bias_s : float[16]         64 B
//   wih_s  : float[16]         64 B
//   red    : float[512]      2048 B   reductions
#define SMEM_BYTES (65536 + 8192 + 2048 + 64 + 64 + 2048)

__global__ void __launch_bounds__(NTH, 1)
lstm_attn_kernel(const float* __restrict__ inseq,
                 const float* __restrict__ h0,   const float* __restrict__ c0,
                 const float* __restrict__ Wih,  const float* __restrict__ Whh,
                 const float* __restrict__ bih,  const float* __restrict__ bhh,
                 const float* __restrict__ rWih, const float* __restrict__ rWhh,
                 const float* __restrict__ rbih, const float* __restrict__ rbhh,
                 const float* __restrict__ linW, const float* __restrict__ linb,
                 float* __restrict__ dout)
{
    extern __shared__ char smem_raw[];
    ull*   Wd     = reinterpret_cast<ull*>(smem_raw);
    float* gsm    = reinterpret_cast<float*>(smem_raw + 65536);
    float* c_s    = gsm + 2048;
    float* bias_s = c_s + JPC * BD;
    float* wih_s  = bias_s + 16;
    float* red    = wih_s + 16;

    const int g   = blockIdx.x;
    const int tid = threadIdx.x;
    const int tx  = tid & 31;   // 4 batch elems: b = 4*tx .. 4*tx+3
    const int ty  = tid >> 5;   // 2 gate rows:  2*ty, 2*ty+1

    // ---- encoder weights: lr = gate*4 + jj; global row = gate*512 + 4g + jj ----
    for (int idx = tid; idx < 16 * HDIM; idx += NTH) {
        int lr = idx >> 9, k = idx & (HDIM - 1);
        int gi = lr >> 2, jj = lr & 3;
        float w = Whh[(size_t)(gi * HDIM + JPC * g + jj) * HDIM + k];
        Wd[lr * HDIM + k] = pk(w, w);
    }
    if (tid < 16) {
        int gi = tid >> 2, jj = tid & 3;
        int row = gi * HDIM + JPC * g + jj;
        bias_s[tid] = bih[row] + bhh[row];
        wih_s[tid]  = Wih[row];            // I == 1
    }
    for (int q = tid; q < JPC * BD; q += NTH) {
        int jj = q >> 7, b = q & (BD - 1);
        c_s[q] = c0[b * HDIM + JPC * g + jj];
        g_h[0][(JPC * g + jj) * BD + b] = h0[b * HDIM + JPC * g + jj];
    }
    grid_sync();

    int cur = 0;
    // ======================= encoder: 512 LSTM steps =======================
    for (int t = 0; t < TENC; ++t) {
        const int nxt = cur ^ 1;
        ull a00 = 0ull, a01 = 0ull, a10 = 0ull, a11 = 0ull;
        const float* hb  = g_h[cur];
        const ull*   w0p = Wd + (2 * ty) * HDIM;
        const ull*   w1p = Wd + (2 * ty + 1) * HDIM;
        #pragma unroll 4
        for (int k = 0; k < HDIM; ++k) {
            double2 hv = __ldcg(reinterpret_cast<const double2*>(hb + k * BD + tx * 4));
            ull hx = (ull)__double_as_longlong(hv.x);
            ull hy = (ull)__double_as_longlong(hv.y);
            ull w0 = w0p[k], w1 = w1p[k];
            fma2(a00, w0, hx); fma2(a01, w0, hy);
            fma2(a10, w1, hx); fma2(a11, w1, hy);
        }
        float4 xv = *reinterpret_cast<const float4*>(inseq + t * BD + tx * 4);
        float2 f00 = upk(a00), f01 = upk(a01), f10 = upk(a10), f11 = upk(a11);
        int r0 = 2 * ty, r1 = r0 + 1;
        float wi0 = wih_s[r0], bb0 = bias_s[r0];
        float wi1 = wih_s[r1], bb1 = bias_s[r1];
        *reinterpret_cast<float4*>(gsm + r0 * BD + tx * 4) =
            make_float4(f00.x + xv.x * wi0 + bb0, f00.y + xv.y * wi0 + bb0,
                        f01.x + xv.z * wi0 + bb0, f01.y + xv.w * wi0 + bb0);
        *reinterpret_cast<float4*>(gsm + r1 * BD + tx * 4) =
            make_float4(f10.x + xv.x * wi1 + bb1, f10.y + xv.y * wi1 + bb1,
                        f11.x + xv.z * wi1 + bb1, f11.y + xv.w * wi1 + bb1);
        __syncthreads();
        #pragma unroll
        for (int q = tid; q < JPC * BD; q += NTH) {
            int jj = q >> 7, b = q & (BD - 1);
            float ig = sigf (gsm[( 0 + jj) * BD + b]);
            float fg = sigf (gsm[( 4 + jj) * BD + b]);
            float gg = tanhf(gsm[( 8 + jj) * BD + b]);
            float og = sigf (gsm[(12 + jj) * BD + b]);
            float c = fg * c_s[q] + ig * gg;
            float h = og * tanhf(c);
            c_s[q] = c;
            __stcg(&g_h[nxt][(JPC * g + jj) * BD + b], h);
            g_enc[((size_t)t * HDIM + JPC * g + jj) * BD + b] = h;
        }
        grid_sync();
        cur = nxt;
    }
    // final encoder hidden now resides in g_h[0] (cur == 0)

    // ======= precompute p[t][b] = enc_t[b].linW; x0; load decoder weights =======
    for (int idx = tid; idx < HDIM; idx += NTH) gsm[idx] = linW[idx];
    __syncthreads();
    for (int tt = 0; tt < 4; ++tt) {
        int t = g + tt * NCTA;
        int b = tid & (BD - 1), hf = tid >> 7;
        const float* ep = g_enc + ((size_t)t * HDIM + hf * 256) * BD + b;
        float acc = 0.0f;
        #pragma unroll 4
        for (int j = 0; j < 256; ++j)
            acc += ep[(size_t)j * BD] * gsm[hf * 256 + j];
        red[hf * BD + b] = acc;
        __syncthreads();
        if (hf == 0) g_p[t * BD + b] = red[b] + red[BD + b];
        __syncthreads();
    }
    if (g == 0 && tid < BD) g_x[tid] = inseq[TENC * BD + tid];  // x0 = input_seq[-1]
    for (int idx = tid; idx < JPC * HDIM; idx += NTH) {
        int lr = idx >> 9, k = idx & (HDIM - 1);
        float w = rWhh[(size_t)(JPC * g + lr) * HDIM + k];
        Wd[lr * HDIM + k] = pk(w, w);
    }
    if (tid < JPC) {
        int row = JPC * g + tid;
        bias_s[tid] = rbih[row] + rbhh[row];
        wih_s[tid]  = rWih[row];           // O == 1
    }
    grid_sync();

    // ======================= decoder: 32 steps =======================
    cur = 0;
    for (int s = 0; s < PRED; ++s) {
        const int nxt = cur ^ 1;
        // --- RNN matvec: h_new[4g+jj][b] = tanh(x[b]*rWih + rb + rWhh_row . h_old) ---
        {
            int jj = tid >> 6, bb = tid & 63;
            ull acc = 0ull;
            const float* hb = g_h[cur];
            const ull*   wp = Wd + jj * HDIM;
            #pragma unroll 4
            for (int k = 0; k < HDIM; ++k) {
                double hv = __ldcg(reinterpret_cast<const double*>(hb + k * BD + bb * 2));
                fma2(acc, wp[k], (ull)__double_as_longlong(hv));
            }
            float2 f = upk(acc);
            float rwi = wih_s[jj], rb = bias_s[jj];
            int b0 = 2 * bb;
            float x0v = __ldcg(g_x + b0), x1v = __ldcg(g_x + b0 + 1);
            __stcg(&g_h[nxt][(JPC * g + jj) * BD + b0],     tanhf(f.x + x0v * rwi + rb));
            __stcg(&g_h[nxt][(JPC * g + jj) * BD + b0 + 1], tanhf(f.y + x1v * rwi + rb));
        }
        grid_sync();
        // --- scores[t][b] = enc_t[b] . h_new[b] for t in {g, g+128, g+256, g+384} ---
        for (int tt = 0; tt < 4; ++tt) {
            int t = g + tt * NCTA;
            int b = tid & (BD - 1), hf = tid >> 7;
            const float* ep = g_enc + ((size_t)t * HDIM + hf * 256) * BD + b;
            const float* hp = g_h[nxt] + hf * 256 * BD + b;
            float acc = 0.0f;
            #pragma unroll 4
            for (int j = 0; j < 256; ++j)
                acc += ep[(size_t)j * BD] * __ldcg(hp + j * BD);
            red[hf * BD + b] = acc;
            __syncthreads();
            if (hf == 0) g_sc[t * BD + b] = red[b] + red[BD + b];
            __syncthreads();
        }
        grid_sync();
        // --- softmax over t + output, CTA g owns batch element b = g ---
        {
            float s1 = __ldcg(g_sc + tid * BD + g);
            float s2 = __ldcg(g_sc + (tid + 256) * BD + g);
            red[tid] = fmaxf(s1, s2);
            __syncthreads();
            for (int off = 128; off > 0; off >>= 1) {
                if (tid < off) red[tid] = fmaxf(red[tid], red[tid + off]);
                __syncthreads();
            }
            float mall = red[0];
            __syncthreads();
            float e1 = expf(s1 - mall), e2 = expf(s2 - mall);
            float wp2 = e1 * g_p[tid * BD + g] + e2 * g_p[(tid + 256) * BD + g];
            red[tid] = e1 + e2;
            gsm[tid] = wp2;
            __syncthreads();
            for (int off = 128; off > 0; off >>= 1) {
                if (tid < off) { red[tid] += red[tid + off]; gsm[tid] += gsm[tid + off]; }
                __syncthreads();
            }
            if (tid == 0) {
                float o = fmaxf(0.0f, gsm[0] / red[0] + linb[0]);
                dout[s * BD + g] = o;
                __stcg(&g_x[g], o);
            }
        }
        grid_sync();
        cur = nxt;
    }
}

extern "C" void kernel_launch(void* const* d_in, const int* in_sizes, int n_in,
                              void* d_out, int out_size) {
    (void)in_sizes; (void)n_in; (void)out_size;
    cudaFuncSetAttribute(lstm_attn_kernel,
                         cudaFuncAttributeMaxDynamicSharedMemorySize, SMEM_BYTES);
    const float* inseq = (const float*)d_in[0];
    const float* h0    = (const float*)d_in[1];
    const float* c0    = (const float*)d_in[2];
    const float* Wih   = (const float*)d_in[3];
    const float* Whh   = (const float*)d_in[4];
    const float* bih   = (const float*)d_in[5];
    const float* bhh   = (const float*)d_in[6];
    const float* rWih  = (const float*)d_in[7];
    const float* rWhh  = (const float*)d_in[8];
    const float* rbih  = (const float*)d_in[9];
    const float* rbhh  = (const float*)d_in[10];
    const float* linW  = (const float*)d_in[11];
    const float* linb  = (const float*)d_in[12];
    float* dout = (float*)d_out;
    lstm_attn_kernel<<<NCTA, NTH, SMEM_BYTES>>>(
        inseq, h0, c0, Wih, Whh, bih, bhh,
        rWih, rWhh, rbih, rbhh, linW, linb, dout);
}

// round 11
// speedup vs baseline: 2.2222x; 2.2222x over previous
#include <cuda_runtime.h>
#include <cuda_fp16.h>
#include <math.h>

#define NCTA 128
#define NTH  256
#define HDIM 512
#define BD   128
#define TENC 512
#define PRED 32
#define HB   (HDIM * BD)   // floats per h slab

typedef unsigned long long ull;

// ---------------- device scratch (static, no allocation) ----------------
__device__ float  g_hist[(size_t)(TENC + 1) * HB];   // fp32 h history, slab 0 = h0 (134.5MB)
__device__ __half g_ench[(size_t)TENC * HB];         // fp16 enc outputs [t][j][b] (67MB)
__device__ float  g_h[2][HB];                        // decoder RNN hidden ping-pong
__device__ float  g_p[TENC * BD];                    // p[t][b] = enc_t[b] . lin_W
__device__ float  g_sc[TENC * BD];                   // attention scores [t][b]
__device__ float  g_x[BD];                           // decoder input x[b]
__device__ volatile unsigned g_gen = 0;
__device__ unsigned g_cnt = 0;

// ---------------- helpers ----------------
__device__ __forceinline__ void fma2(ull& d, ull a, ull b) {
    asm("fma.rn.f32x2 %0, %1, %2, %0;" : "+l"(d) : "l"(a), "l"(b));
}
__device__ __forceinline__ ull pk(float a, float b) {
    ull r; asm("mov.b64 %0, {%1, %2};" : "=l"(r) : "f"(a), "f"(b)); return r;
}
__device__ __forceinline__ float2 upk(ull v) {
    float2 r; asm("mov.b64 {%0, %1}, %2;" : "=f"(r.x), "=f"(r.y) : "l"(v)); return r;
}
__device__ __forceinline__ float sigf(float x) { return 1.0f / (1.0f + expf(-x)); }

// Software grid barrier: 128 CTAs, 1/SM, all co-resident. Generation-based,
// re-entrant across graph replays.
__device__ __forceinline__ void grid_sync() {
    __syncthreads();
    if (threadIdx.x == 0) {
        __threadfence();
        unsigned gen = g_gen;
        if (atomicAdd(&g_cnt, 1u) == NCTA - 1u) {
            g_cnt = 0u;
            __threadfence();
            g_gen = gen + 1u;
        } else {
            while (g_gen == gen) { __nanosleep(32); }
        }
        __threadfence();
    }
    __syncthreads();
}

// SMEM layout (dynamic, 112768 B):
//   Wd     : ull    65536 B  enc: [k][16] (w,w)-dup rows; dec: [4][512]
//   psum   : ull    32768 B  k-segment partials [kseg][16 rows][64 b-pairs]
//   gsm    : float   8192 B  gate staging / linW
//   c_s    : float   2048 B  cell state
//   bias_s : float     64 B
//   wih_s  : float     64 B
//   red    : float   4096 B  reductions
#define SMEM_BYTES (65536 + 32768 + 8192 + 2048 + 64 + 64 + 4096)

__global__ void __launch_bounds__(NTH, 1)
lstm_attn_kernel(const float* __restrict__ inseq,
                 const float* __restrict__ h0,   const float* __restrict__ c0,
                 const float* __restrict__ Wih,  const float* __restrict__ Whh,
                 const float* __restrict__ bih,  const float* __restrict__ bhh,
                 const float* __restrict__ rWih, const float* __restrict__ rWhh,
                 const float* __restrict__ rbih, const float* __restrict__ rbhh,
                 const float* __restrict__ linW, const float* __restrict__ linb,
                 float* __restrict__ dout)
{
    extern __shared__ char smem_raw[];
    ull*   Wd     = reinterpret_cast<ull*>(smem_raw);
    ull*   psum   = reinterpret_cast<ull*>(smem_raw + 65536);
    float* psum_f = reinterpret_cast<float*>(psum);
    float* gsm    = reinterpret_cast<float*>(smem_raw + 65536 + 32768);
    float* c_s    = gsm + 2048;
    float* bias_s = c_s + 512;
    float* wih_s  = bias_s + 16;
    float* red    = wih_s + 16;
    float2* red2  = reinterpret_cast<float2*>(red);

    const int g    = blockIdx.x;
    const int tid  = threadIdx.x;
    const int lane = tid & 31;
    const int wrp  = tid >> 5;
    const int kseg = wrp & 3;     // k segment [128*kseg, 128*kseg+128)
    const int rhalf= wrp >> 2;    // rows rhalf*8 .. rhalf*8+7

    // ---- encoder weights: Wd[k][16] with r = gate*4 + jj ----
    for (int idx = tid; idx < 16 * HDIM; idx += NTH) {
        int k = idx >> 4, r = idx & 15;
        int gi = r >> 2, jj = r & 3;
        float w = Whh[(size_t)(gi * HDIM + 4 * g + jj) * HDIM + k];
        Wd[k * 16 + r] = pk(w, w);
    }
    if (tid < 16) {
        int gi = tid >> 2, jj = tid & 3;
        int row = gi * HDIM + 4 * g + jj;
        bias_s[tid] = bih[row] + bhh[row];
        wih_s[tid]  = Wih[row];            // I == 1
    }
    for (int q = tid; q < 512; q += NTH) {
        int jj = q >> 7, b = q & 127;
        c_s[q] = c0[b * HDIM + 4 * g + jj];
        g_hist[(4 * g + jj) * BD + b] = h0[b * HDIM + 4 * g + jj];  // slab 0
    }
    grid_sync();

    // ======================= encoder: 512 LSTM steps =======================
    for (int t = 0; t < TENC; ++t) {
        // --- matvec: 8 rows x 4 batch per thread, k split across 4 warp pairs ---
        const float* hbase = g_hist + (size_t)t * HB + (kseg * 128) * BD + 4 * lane;
        const ull*   wbase = Wd + (kseg * 128) * 16 + rhalf * 8;
        ull acc[8][2];
        #pragma unroll
        for (int r = 0; r < 8; ++r) { acc[r][0] = 0ull; acc[r][1] = 0ull; }
        #pragma unroll 4
        for (int kk = 0; kk < 128; ++kk) {
            double2 hv = *reinterpret_cast<const double2*>(hbase + kk * BD);
            ull hx = (ull)__double_as_longlong(hv.x);
            ull hy = (ull)__double_as_longlong(hv.y);
            const ull* wp = wbase + kk * 16;
            #pragma unroll
            for (int r = 0; r < 8; ++r) {
                ull w = wp[r];
                fma2(acc[r][0], w, hx);
                fma2(acc[r][1], w, hy);
            }
        }
        // partials -> SMEM: psum[kseg][rhalf*8+r][lane*2 + p]
        #pragma unroll
        for (int r = 0; r < 8; ++r) {
            psum[(kseg * 16 + rhalf * 8 + r) * 64 + lane * 2    ] = acc[r][0];
            psum[(kseg * 16 + rhalf * 8 + r) * 64 + lane * 2 + 1] = acc[r][1];
        }
        __syncthreads();
        // --- phase1: sum 4 k-segments + input/bias -> gates gsm[row*128+b] ---
        {
            float xv = inseq[t * BD + (tid & 127)];  // b == tid&127 for all i
            #pragma unroll
            for (int i = 0; i < 8; ++i) {
                int q = tid + i * NTH;               // q = row*128 + b
                int row = q >> 7;
                float s = psum_f[q] + psum_f[2048 + q] + psum_f[4096 + q] + psum_f[6144 + q];
                gsm[q] = s + xv * wih_s[row] + bias_s[row];
            }
        }
        __syncthreads();
        // --- phase2: LSTM cell update + write h (fp32 history + fp16 copy) ---
        #pragma unroll
        for (int q = tid; q < 512; q += NTH) {
            int jj = q >> 7, b = q & 127;
            float ig = sigf (gsm[( 0 + jj) * BD + b]);
            float fg = sigf (gsm[( 4 + jj) * BD + b]);
            float gg = tanhf(gsm[( 8 + jj) * BD + b]);
            float og = sigf (gsm[(12 + jj) * BD + b]);
            float c = fg * c_s[q] + ig * gg;
            float h = og * tanhf(c);
            c_s[q] = c;
            g_hist[(size_t)(t + 1) * HB + (4 * g + jj) * BD + b] = h;
            g_ench[(size_t)t * HB + (4 * g + jj) * BD + b] = __float2half(h);
        }
        grid_sync();
    }

    // ======= precompute p[t][b] = enc_t[b].linW (fp16 enc); x0; dec weights =======
    for (int idx = tid; idx < HDIM; idx += NTH) gsm[idx] = linW[idx];
    __syncthreads();
    for (int tt = 0; tt < 4; ++tt) {
        int t = g + tt * NCTA;
        int b2 = tid & 63, hf = tid >> 6;
        const __half2* ep = reinterpret_cast<const __half2*>(g_ench + (size_t)t * HB)
                            + (hf * 128) * 64 + b2;
        float2 a = make_float2(0.0f, 0.0f);
        #pragma unroll 4
        for (int j = 0; j < 128; ++j) {
            float2 hv = __half22float2(ep[j * 64]);
            float lw = gsm[hf * 128 + j];
            a.x += hv.x * lw; a.y += hv.y * lw;
        }
        red2[hf * 64 + b2] = a;
        __syncthreads();
        if (hf == 0) {
            float2 r0 = red2[b2], r1 = red2[64 + b2], r2 = red2[128 + b2], r3 = red2[192 + b2];
            g_p[t * BD + 2 * b2]     = r0.x + r1.x + r2.x + r3.x;
            g_p[t * BD + 2 * b2 + 1] = r0.y + r1.y + r2.y + r3.y;
        }
        __syncthreads();
    }
    if (g == 0 && tid < BD) g_x[tid] = inseq[TENC * BD + tid];  // x0 = input_seq[-1]
    // decoder weights: Wd[lr][k], lr = 0..3 (rows 4g..4g+3)
    for (int idx = tid; idx < 4 * HDIM; idx += NTH) {
        int lr = idx >> 9, k = idx & (HDIM - 1);
        float w = rWhh[(size_t)(4 * g + lr) * HDIM + k];
        Wd[lr * HDIM + k] = pk(w, w);
    }
    if (tid < 4) {
        int row = 4 * g + tid;
        bias_s[tid] = rbih[row] + rbhh[row];
        wih_s[tid]  = rWih[row];           // O == 1
    }
    grid_sync();

    // ======================= decoder: 32 steps =======================
    int cur = 0;
    for (int s = 0; s < PRED; ++s) {
        const int nxt = cur ^ 1;
        // --- RNN matvec: h_new[4g+jj][b] = tanh(x[b]*rWih + rb + rWhh_row . h_old) ---
        {
            int jj = tid >> 6, bb = tid & 63;
            ull acc = 0ull;
            const float* hb = (s == 0) ? (g_hist + (size_t)TENC * HB) : g_h[cur];
            const ull*   wp = Wd + jj * HDIM;
            #pragma unroll 4
            for (int k = 0; k < HDIM; ++k) {
                double hv = __ldcg(reinterpret_cast<const double*>(hb + k * BD + bb * 2));
                fma2(acc, wp[k], (ull)__double_as_longlong(hv));
            }
            float2 f = upk(acc);
            float rwi = wih_s[jj], rb = bias_s[jj];
            int b0 = 2 * bb;
            float x0v = __ldcg(g_x + b0), x1v = __ldcg(g_x + b0 + 1);
            __stcg(&g_h[nxt][(4 * g + jj) * BD + b0],     tanhf(f.x + x0v * rwi + rb));
            __stcg(&g_h[nxt][(4 * g + jj) * BD + b0 + 1], tanhf(f.y + x1v * rwi + rb));
        }
        grid_sync();
        // --- scores[t][b] = enc_t[b] . h_new[b], enc in fp16 (L2-resident) ---
        for (int tt = 0; tt < 4; ++tt) {
            int t = g + tt * NCTA;
            int b2 = tid & 63, hf = tid >> 6;
            const __half2* ep = reinterpret_cast<const __half2*>(g_ench + (size_t)t * HB)
                                + (hf * 128) * 64 + b2;
            const float2* hp = reinterpret_cast<const float2*>(g_h[nxt]) + (hf * 128) * 64 + b2;
            float2 a = make_float2(0.0f, 0.0f);
            #pragma unroll 4
            for (int j = 0; j < 128; ++j) {
                float2 hv = __half22float2(ep[j * 64]);
                float2 hh = __ldcg(hp + j * 64);
                a.x += hv.x * hh.x; a.y += hv.y * hh.y;
            }
            red2[hf * 64 + b2] = a;
            __syncthreads();
            if (hf == 0) {
                float2 r0 = red2[b2], r1 = red2[64 + b2], r2 = red2[128 + b2], r3 = red2[192 + b2];
                g_sc[t * BD + 2 * b2]     = r0.x + r1.x + r2.x + r3.x;
                g_sc[t * BD + 2 * b2 + 1] = r0.y + r1.y + r2.y + r3.y;
            }
            __syncthreads();
        }
        grid_sync();
        // --- softmax over t + output; CTA g owns batch element b = g ---
        {
            float s1 = __ldcg(g_sc + tid * BD + g);
            float s2 = __ldcg(g_sc + (tid + 256) * BD + g);
            red[tid] = fmaxf(s1, s2);
            __syncthreads();
            for (int off = 128; off > 0; off >>= 1) {
                if (tid < off) red[tid] = fmaxf(red[tid], red[tid + off]);
                __syncthreads();
            }
            float mall = red[0];
            __syncthreads();
            float e1 = expf(s1 - mall), e2 = expf(s2 - mall);
            float wp2 = e1 * g_p[tid * BD + g] + e2 * g_p[(tid + 256) * BD + g];
            red[tid] = e1 + e2;
            gsm[tid] = wp2;
            __syncthreads();
            for (int off = 128; off > 0; off >>= 1) {
                if (tid < off) { red[tid] += red[tid + off]; gsm[tid] += gsm[tid + off]; }
                __syncthreads();
            }
            if (tid == 0) {
                float o = fmaxf(0.0f, gsm[0] / red[0] + linb[0]);
                dout[s * BD + g] = o;
                __stcg(&g_x[g], o);
            }
        }
        grid_sync();
        cur = nxt;
    }
}

extern "C" void kernel_launch(void* const* d_in, const int* in_sizes, int n_in,
                              void* d_out, int out_size) {
    (void)in_sizes; (void)n_in; (void)out_size;
    cudaFuncSetAttribute(lstm_attn_kernel,
                         cudaFuncAttributeMaxDynamicSharedMemorySize, SMEM_BYTES);
    const float* inseq = (const float*)d_in[0];
    const float* h0    = (const float*)d_in[1];
    const float* c0    = (const float*)d_in[2];
    const float* Wih   = (const float*)d_in[3];
    const float* Whh   = (const float*)d_in[4];
    const float* bih   = (const float*)d_in[5];
    const float* bhh   = (const float*)d_in[6];
    const float* rWih  = (const float*)d_in[7];
    const float* rWhh  = (const float*)d_in[8];
    const float* rbih  = (const float*)d_in[9];
    const float* rbhh  = (const float*)d_in[10];
    const float* linW  = (const float*)d_in[11];
    const float* linb  = (const float*)d_in[12];
    float* dout = (float*)d_out;
    lstm_attn_kernel<<<NCTA, NTH, SMEM_BYTES>>>(
        inseq, h0, c0, Wih, Whh, bih, bhh,
        rWih, rWhh, rbih, rbhh, linW, linb, dout);
}

// round 12
// speedup vs baseline: 3.2173x; 1.4478x over previous
#include <cuda_runtime.h>
#include <cuda_fp16.h>
#include <math.h>

#define NCTA 128
#define NTH  512
#define HDIM 512
#define BD   128
#define TENC 512
#define PRED 32
#define HB   (HDIM * BD)   // floats per h slab

typedef unsigned long long ull;

// ---------------- device scratch (static, no allocation) ----------------
__device__ float  g_hist[(size_t)(TENC + 1) * HB];   // fp32 h history, slab 0 = h0 (134.5MB)
__device__ __half g_ench[(size_t)TENC * HB];         // fp16 enc outputs [t][j][b] (67MB)
__device__ float  g_h[2][HB];                        // decoder RNN hidden ping-pong
__device__ float  g_p[TENC * BD];                    // p[t][b] = enc_t[b] . lin_W
__device__ float  g_sc[TENC * BD];                   // attention scores [t][b]
__device__ float  g_x[BD];                           // decoder input x[b]
__device__ volatile unsigned g_gen = 0;
__device__ unsigned g_cnt = 0;

// ---------------- helpers ----------------
__device__ __forceinline__ void fma2(ull& d, ull a, ull b) {
    asm("fma.rn.f32x2 %0, %1, %2, %0;" : "+l"(d) : "l"(a), "l"(b));
}
__device__ __forceinline__ ull pk(float a, float b) {
    ull r; asm("mov.b64 %0, {%1, %2};" : "=l"(r) : "f"(a), "f"(b)); return r;
}
__device__ __forceinline__ float2 upk(ull v) {
    float2 r; asm("mov.b64 {%0, %1}, %2;" : "=f"(r.x), "=f"(r.y) : "l"(v)); return r;
}
__device__ __forceinline__ float sigf(float x) { return 1.0f / (1.0f + expf(-x)); }

// Software grid barrier: 128 CTAs, 1/SM, all co-resident. Generation-based,
// re-entrant across graph replays. (Proven in R10/R11.)
__device__ __forceinline__ void grid_sync() {
    __syncthreads();
    if (threadIdx.x == 0) {
        __threadfence();
        unsigned gen = g_gen;
        if (atomicAdd(&g_cnt, 1u) == NCTA - 1u) {
            g_cnt = 0u;
            __threadfence();
            g_gen = gen + 1u;
        } else {
            while (g_gen == gen) { __nanosleep(32); }
        }
        __threadfence();
    }
    __syncthreads();
}

// SMEM layout (dynamic, 145536 B):
//   Wd     : ull    65536 B  enc: [k][16] (w,w)-dup rows; dec: [4][512]
//   psum   : ull    65536 B  k-segment partials [8 seg][16 rows][32 ull2]
//   gsm    : float   8192 B  gate staging / linW
//   c_s    : float   2048 B  cell state
//   bias_s : float     64 B
//   wih_s  : float     64 B
//   red    : float   4096 B  reductions
#define SMEM_BYTES (65536 + 65536 + 8192 + 2048 + 64 + 64 + 4096)

__global__ void __launch_bounds__(NTH, 1)
lstm_attn_kernel(const float* __restrict__ inseq,
                 const float* __restrict__ h0,   const float* __restrict__ c0,
                 const float* __restrict__ Wih,  const float* __restrict__ Whh,
                 const float* __restrict__ bih,  const float* __restrict__ bhh,
                 const float* __restrict__ rWih, const float* __restrict__ rWhh,
                 const float* __restrict__ rbih, const float* __restrict__ rbhh,
                 const float* __restrict__ linW, const float* __restrict__ linb,
                 float* __restrict__ dout)
{
    extern __shared__ char smem_raw[];
    ull*        Wd     = reinterpret_cast<ull*>(smem_raw);
    ull*        psum   = reinterpret_cast<ull*>(smem_raw + 65536);
    ulonglong2* psum2  = reinterpret_cast<ulonglong2*>(psum);
    float*      psum_f = reinterpret_cast<float*>(psum);
    float*      gsm    = reinterpret_cast<float*>(smem_raw + 131072);
    float*      c_s    = gsm + 2048;
    float*      bias_s = c_s + 512;
    float*      wih_s  = bias_s + 16;
    float*      red    = wih_s + 16;
    float2*     red2   = reinterpret_cast<float2*>(red);

    const int g    = blockIdx.x;
    const int tid  = threadIdx.x;
    const int lane = tid & 31;
    const int wrp  = tid >> 5;
    const int kseg = wrp & 7;     // k segment [64*kseg, 64*kseg+64)
    const int rhalf= wrp >> 3;    // rows rhalf*8 .. rhalf*8+7

    // ---- encoder weights: Wd[k][16] with r = gate*4 + jj ----
    for (int idx = tid; idx < 16 * HDIM; idx += NTH) {
        int k = idx >> 4, r = idx & 15;
        int gi = r >> 2, jj = r & 3;
        float w = Whh[(size_t)(gi * HDIM + 4 * g + jj) * HDIM + k];
        Wd[k * 16 + r] = pk(w, w);
    }
    if (tid < 16) {
        int gi = tid >> 2, jj = tid & 3;
        int row = gi * HDIM + 4 * g + jj;
        bias_s[tid] = bih[row] + bhh[row];
        wih_s[tid]  = Wih[row];            // I == 1
    }
    for (int q = tid; q < 512; q += NTH) {
        int jj = q >> 7, b = q & 127;
        c_s[q] = c0[b * HDIM + 4 * g + jj];
        g_hist[(4 * g + jj) * BD + b] = h0[b * HDIM + 4 * g + jj];  // slab 0
    }
    grid_sync();

    // ======================= encoder: 512 LSTM steps =======================
    for (int t = 0; t < TENC; ++t) {
        // --- matvec: 8 rows x 4 batch per thread; k split across 8 segments,
        //     rows split across 2 halves (16 warps total) ---
        const float* hbase = g_hist + (size_t)t * HB + (kseg * 64) * BD + 4 * lane;
        const ull*   wbase = Wd + (kseg * 64) * 16 + rhalf * 8;
        ull acc[8][2];
        #pragma unroll
        for (int r = 0; r < 8; ++r) { acc[r][0] = 0ull; acc[r][1] = 0ull; }
        for (int kb = 0; kb < 64; kb += 4) {
            // explicit MLP=4: all four 16B loads in flight before FMAs
            double2 hv0 = *reinterpret_cast<const double2*>(hbase + (kb + 0) * BD);
            double2 hv1 = *reinterpret_cast<const double2*>(hbase + (kb + 1) * BD);
            double2 hv2 = *reinterpret_cast<const double2*>(hbase + (kb + 2) * BD);
            double2 hv3 = *reinterpret_cast<const double2*>(hbase + (kb + 3) * BD);
            const ull* wp = wbase + kb * 16;
            ull hx, hy;
            hx = (ull)__double_as_longlong(hv0.x); hy = (ull)__double_as_longlong(hv0.y);
            #pragma unroll
            for (int r = 0; r < 8; ++r) { ull w = wp[r];      fma2(acc[r][0], w, hx); fma2(acc[r][1], w, hy); }
            hx = (ull)__double_as_longlong(hv1.x); hy = (ull)__double_as_longlong(hv1.y);
            #pragma unroll
            for (int r = 0; r < 8; ++r) { ull w = wp[16 + r]; fma2(acc[r][0], w, hx); fma2(acc[r][1], w, hy); }
            hx = (ull)__double_as_longlong(hv2.x); hy = (ull)__double_as_longlong(hv2.y);
            #pragma unroll
            for (int r = 0; r < 8; ++r) { ull w = wp[32 + r]; fma2(acc[r][0], w, hx); fma2(acc[r][1], w, hy); }
            hx = (ull)__double_as_longlong(hv3.x); hy = (ull)__double_as_longlong(hv3.y);
            #pragma unroll
            for (int r = 0; r < 8; ++r) { ull w = wp[48 + r]; fma2(acc[r][0], w, hx); fma2(acc[r][1], w, hy); }
        }
        // partials -> SMEM: psum2[(kseg*16 + row)*32 + lane]
        #pragma unroll
        for (int r = 0; r < 8; ++r) {
            psum2[(kseg * 16 + rhalf * 8 + r) * 32 + lane] =
                make_ulonglong2(acc[r][0], acc[r][1]);
        }
        __syncthreads();
        // --- phase1: sum 8 k-segments + input/bias -> gates gsm[row*128+b] ---
        {
            float xv = inseq[t * BD + (tid & 127)];
            #pragma unroll
            for (int i = 0; i < 4; ++i) {
                int q = tid + i * NTH;               // q = row*128 + b
                int row = q >> 7;
                float s = psum_f[q]          + psum_f[2048 + q]
                        + psum_f[2*2048 + q] + psum_f[3*2048 + q]
                        + psum_f[4*2048 + q] + psum_f[5*2048 + q]
                        + psum_f[6*2048 + q] + psum_f[7*2048 + q];
                gsm[q] = s + xv * wih_s[row] + bias_s[row];
            }
        }
        __syncthreads();
        // --- phase2: LSTM cell update + write h (fp32 history + fp16 copy) ---
        {
            int q = tid;                              // exactly 512 cells
            int jj = q >> 7, b = q & 127;
            float ig = sigf (gsm[( 0 + jj) * BD + b]);
            float fg = sigf (gsm[( 4 + jj) * BD + b]);
            float gg = tanhf(gsm[( 8 + jj) * BD + b]);
            float og = sigf (gsm[(12 + jj) * BD + b]);
            float c = fg * c_s[q] + ig * gg;
            float h = og * tanhf(c);
            c_s[q] = c;
            g_hist[(size_t)(t + 1) * HB + (4 * g + jj) * BD + b] = h;
            g_ench[(size_t)t * HB + (4 * g + jj) * BD + b] = __float2half(h);
        }
        grid_sync();
    }

    // ======= precompute p[t][b] = enc_t[b].linW (fp16 enc); x0; dec weights =======
    for (int idx = tid; idx < HDIM; idx += NTH) gsm[idx] = linW[idx];
    __syncthreads();
    for (int tt = 0; tt < 4; ++tt) {
        int t = g + tt * NCTA;
        int b2 = tid & 63, hf = tid >> 6;   // 8 chunks of 64 j-rows
        const __half2* ep = reinterpret_cast<const __half2*>(g_ench + (size_t)t * HB)
                            + (hf * 64) * 64 + b2;
        float2 a = make_float2(0.0f, 0.0f);
        #pragma unroll 4
        for (int j = 0; j < 64; ++j) {
            float2 hv = __half22float2(ep[j * 64]);
            float lw = gsm[hf * 64 + j];
            a.x += hv.x * lw; a.y += hv.y * lw;
        }
        red2[hf * 64 + b2] = a;
        __syncthreads();
        if (hf == 0) {
            float sx = 0.0f, sy = 0.0f;
            #pragma unroll
            for (int c = 0; c < 8; ++c) { float2 r = red2[c * 64 + b2]; sx += r.x; sy += r.y; }
            g_p[t * BD + 2 * b2]     = sx;
            g_p[t * BD + 2 * b2 + 1] = sy;
        }
        __syncthreads();
    }
    if (g == 0 && tid < BD) g_x[tid] = inseq[TENC * BD + tid];  // x0 = input_seq[-1]
    // decoder weights: Wd[lr][k] (w,w)-dup, lr = 0..3 (rows 4g..4g+3)
    for (int idx = tid; idx < 4 * HDIM; idx += NTH) {
        int lr = idx >> 9, k = idx & (HDIM - 1);
        float w = rWhh[(size_t)(4 * g + lr) * HDIM + k];
        Wd[lr * HDIM + k] = pk(w, w);
    }
    if (tid < 4) {
        int row = 4 * g + tid;
        bias_s[tid] = rbih[row] + rbhh[row];
        wih_s[tid]  = rWih[row];           // O == 1
    }
    grid_sync();

    // ======================= decoder: 32 steps =======================
    int cur = 0;
    for (int s = 0; s < PRED; ++s) {
        const int nxt = cur ^ 1;
        // --- RNN matvec (256 threads): h_new = tanh(x*rWih + rb + rWhh.h_old) ---
        if (tid < 256) {
            int jj = tid >> 6, bb = tid & 63;
            ull acc = 0ull;
            const float* hb = (s == 0) ? (g_hist + (size_t)TENC * HB) : g_h[cur];
            const ull*   wp = Wd + jj * HDIM;
            #pragma unroll 4
            for (int k = 0; k < HDIM; ++k) {
                double hv = __ldcg(reinterpret_cast<const double*>(hb + k * BD + bb * 2));
                fma2(acc, wp[k], (ull)__double_as_longlong(hv));
            }
            float2 f = upk(acc);
            float rwi = wih_s[jj], rb = bias_s[jj];
            int b0 = 2 * bb;
            float x0v = __ldcg(g_x + b0), x1v = __ldcg(g_x + b0 + 1);
            __stcg(&g_h[nxt][(4 * g + jj) * BD + b0],     tanhf(f.x + x0v * rwi + rb));
            __stcg(&g_h[nxt][(4 * g + jj) * BD + b0 + 1], tanhf(f.y + x1v * rwi + rb));
        }
        grid_sync();
        // --- scores[t][b] = enc_t[b] . h_new[b], enc fp16 (L2-resident) ---
        for (int tt = 0; tt < 4; ++tt) {
            int t = g + tt * NCTA;
            int b2 = tid & 63, hf = tid >> 6;
            const __half2* ep = reinterpret_cast<const __half2*>(g_ench + (size_t)t * HB)
                                + (hf * 64) * 64 + b2;
            const float2* hp = reinterpret_cast<const float2*>(g_h[nxt]) + (hf * 64) * 64 + b2;
            float2 a = make_float2(0.0f, 0.0f);
            #pragma unroll 4
            for (int j = 0; j < 64; ++j) {
                float2 hv = __half22float2(ep[j * 64]);
                float2 hh = __ldcg(hp + j * 64);
                a.x += hv.x * hh.x; a.y += hv.y * hh.y;
            }
            red2[hf * 64 + b2] = a;
            __syncthreads();
            if (hf == 0) {
                float sx = 0.0f, sy = 0.0f;
                #pragma unroll
                for (int c = 0; c < 8; ++c) { float2 r = red2[c * 64 + b2]; sx += r.x; sy += r.y; }
                g_sc[t * BD + 2 * b2]     = sx;
                g_sc[t * BD + 2 * b2 + 1] = sy;
            }
            __syncthreads();
        }
        grid_sync();
        // --- softmax over t + output; CTA g owns batch element b = g ---
        {
            float s1 = __ldcg(g_sc + tid * BD + g);   // tid covers all 512 t
            red[tid] = s1;
            __syncthreads();
            for (int off = 256; off > 0; off >>= 1) {
                if (tid < off) red[tid] = fmaxf(red[tid], red[tid + off]);
                __syncthreads();
            }
            float mall = red[0];
            __syncthreads();
            float e1 = expf(s1 - mall);
            float wp1 = e1 * g_p[tid * BD + g];
            red[tid] = e1;
            gsm[tid] = wp1;
            __syncthreads();
            for (int off = 256; off > 0; off >>= 1) {
                if (tid < off) { red[tid] += red[tid + off]; gsm[tid] += gsm[tid + off]; }
                __syncthreads();
            }
            if (tid == 0) {
                float o = fmaxf(0.0f, gsm[0] / red[0] + linb[0]);
                dout[s * BD + g] = o;
                __stcg(&g_x[g], o);
            }
        }
        grid_sync();
        cur = nxt;
    }
}

extern "C" void kernel_launch(void* const* d_in, const int* in_sizes, int n_in,
                              void* d_out, int out_size) {
    (void)in_sizes; (void)n_in; (void)out_size;
    cudaFuncSetAttribute(lstm_attn_kernel,
                         cudaFuncAttributeMaxDynamicSharedMemorySize, SMEM_BYTES);
    const float* inseq = (const float*)d_in[0];
    const float* h0    = (const float*)d_in[1];
    const float* c0    = (const float*)d_in[2];
    const float* Wih   = (const float*)d_in[3];
    const float* Whh   = (const float*)d_in[4];
    const float* bih   = (const float*)d_in[5];
    const float* bhh   = (const float*)d_in[6];
    const float* rWih  = (const float*)d_in[7];
    const float* rWhh  = (const float*)d_in[8];
    const float* rbih  = (const float*)d_in[9];
    const float* rbhh  = (const float*)d_in[10];
    const float* linW  = (const float*)d_in[11];
    const float* linb  = (const float*)d_in[12];
    float* dout = (float*)d_out;
    lstm_attn_kernel<<<NCTA, NTH, SMEM_BYTES>>>(
        inseq, h0, c0, Wih, Whh, bih, bhh,
        rWih, rWhh, rbih, rbhh, linW, linb, dout);
}

// round 13
// speedup vs baseline: 3.4630x; 1.0764x over previous
#include <cuda_runtime.h>
#include <cuda_fp16.h>
#include <math.h>

#define NCTA 128
#define NTH  512
#define HDIM 512
#define BD   128
#define TENC 512
#define PRED 32
#define HB   (HDIM * BD)   // floats per h slab

typedef unsigned long long ull;

// ---------------- device scratch (static, no allocation) ----------------
__device__ float  g_hist[(size_t)(TENC + 1) * HB];   // fp32 h history, slab 0 = h0 (134.5MB)
__device__ __half g_ench[(size_t)TENC * HB];         // fp16 enc outputs [t][j][b] (67MB)
__device__ float  g_h[2][HB];                        // decoder RNN hidden ping-pong
__device__ float  g_p[TENC * BD];                    // p[t][b] = enc_t[b] . lin_W
__device__ float  g_sc[TENC * BD];                   // attention scores [t][b]
__device__ float  g_x[BD];                           // decoder input x[b]
__device__ volatile unsigned g_gen = 0;
__device__ unsigned g_cnt = 0;

// ---------------- helpers ----------------
__device__ __forceinline__ void fma2(ull& d, ull a, ull b) {
    asm("fma.rn.f32x2 %0, %1, %2, %0;" : "+l"(d) : "l"(a), "l"(b));
}
__device__ __forceinline__ ull pk(float a, float b) {
    ull r; asm("mov.b64 %0, {%1, %2};" : "=l"(r) : "f"(a), "f"(b)); return r;
}
__device__ __forceinline__ float2 upk(ull v) {
    float2 r; asm("mov.b64 {%0, %1}, %2;" : "=f"(r.x), "=f"(r.y) : "l"(v)); return r;
}
__device__ __forceinline__ float sigf(float x) { return 1.0f / (1.0f + expf(-x)); }

// Software grid barrier: 128 CTAs, 1/SM, all co-resident. Generation-based,
// re-entrant across graph replays. (Proven in R10-R12.)
__device__ __forceinline__ void grid_sync() {
    __syncthreads();
    if (threadIdx.x == 0) {
        __threadfence();
        unsigned gen = g_gen;
        if (atomicAdd(&g_cnt, 1u) == NCTA - 1u) {
            g_cnt = 0u;
            __threadfence();
            g_gen = gen + 1u;
        } else {
            while (g_gen == gen) { __nanosleep(32); }
        }
        __threadfence();
    }
    __syncthreads();
}

// SMEM layout (dynamic, 145536 B): Wd 64K | psum 64K | gsm 8K | c_s 2K | bias 64 | wih 64 | red 4K
#define SMEM_BYTES (65536 + 65536 + 8192 + 2048 + 64 + 64 + 4096)

__global__ void __launch_bounds__(NTH, 1)
lstm_attn_kernel(const float* __restrict__ inseq,
                 const float* __restrict__ h0,   const float* __restrict__ c0,
                 const float* __restrict__ Wih,  const float* __restrict__ Whh,
                 const float* __restrict__ bih,  const float* __restrict__ bhh,
                 const float* __restrict__ rWih, const float* __restrict__ rWhh,
                 const float* __restrict__ rbih, const float* __restrict__ rbhh,
                 const float* __restrict__ linW, const float* __restrict__ linb,
                 float* __restrict__ dout)
{
    extern __shared__ char smem_raw[];
    ull*        Wd     = reinterpret_cast<ull*>(smem_raw);
    ull*        psum   = reinterpret_cast<ull*>(smem_raw + 65536);
    ulonglong2* psum2  = reinterpret_cast<ulonglong2*>(psum);
    float*      psum_f = reinterpret_cast<float*>(psum);
    float*      gsm    = reinterpret_cast<float*>(smem_raw + 131072);
    float*      c_s    = gsm + 2048;
    float*      bias_s = c_s + 512;
    float*      wih_s  = bias_s + 16;
    float*      red    = wih_s + 16;
    float2*     red2   = reinterpret_cast<float2*>(red);

    const int g    = blockIdx.x;
    const int tid  = threadIdx.x;
    const int lane = tid & 31;
    const int wrp  = tid >> 5;
    const int kseg = wrp & 7;     // k segment [64*kseg, 64*kseg+64)
    const int rhalf= wrp >> 3;    // rows rhalf*8 .. rhalf*8+7

    // ---- encoder weights: Wd[k][16] with r = gate*4 + jj ----
    for (int idx = tid; idx < 16 * HDIM; idx += NTH) {
        int k = idx >> 4, r = idx & 15;
        int gi = r >> 2, jj = r & 3;
        float w = Whh[(size_t)(gi * HDIM + 4 * g + jj) * HDIM + k];
        Wd[k * 16 + r] = pk(w, w);
    }
    if (tid < 16) {
        int gi = tid >> 2, jj = tid & 3;
        int row = gi * HDIM + 4 * g + jj;
        bias_s[tid] = bih[row] + bhh[row];
        wih_s[tid]  = Wih[row];            // I == 1
    }
    for (int q = tid; q < 512; q += NTH) {
        int jj = q >> 7, b = q & 127;
        c_s[q] = c0[b * HDIM + 4 * g + jj];
        g_hist[(4 * g + jj) * BD + b] = h0[b * HDIM + 4 * g + jj];  // slab 0
    }
    grid_sync();

    // ======================= encoder: 512 LSTM steps =======================
    for (int t = 0; t < TENC; ++t) {
        // --- matvec: 8 rows x 4 batch per thread; k split 8 segs, rows 2 halves ---
        const float* hbase = g_hist + (size_t)t * HB + (kseg * 64) * BD + 4 * lane;
        const ull*   wbase = Wd + (kseg * 64) * 16 + rhalf * 8;
        ull acc[8][2];
        #pragma unroll
        for (int r = 0; r < 8; ++r) { acc[r][0] = 0ull; acc[r][1] = 0ull; }

        // software pipeline: prefetch batch 0
        double2 c0v = *reinterpret_cast<const double2*>(hbase + 0 * BD);
        double2 c1v = *reinterpret_cast<const double2*>(hbase + 1 * BD);
        double2 c2v = *reinterpret_cast<const double2*>(hbase + 2 * BD);
        double2 c3v = *reinterpret_cast<const double2*>(hbase + 3 * BD);

        for (int kb = 0; kb < 64; kb += 4) {
            // issue next batch's loads before consuming current (wrap on last iter)
            int kn = (kb + 4) & 63;
            double2 n0v = *reinterpret_cast<const double2*>(hbase + (kn + 0) * BD);
            double2 n1v = *reinterpret_cast<const double2*>(hbase + (kn + 1) * BD);
            double2 n2v = *reinterpret_cast<const double2*>(hbase + (kn + 2) * BD);
            double2 n3v = *reinterpret_cast<const double2*>(hbase + (kn + 3) * BD);

            const ulonglong2* wp2 = reinterpret_cast<const ulonglong2*>(wbase + kb * 16);
            ull hx, hy;
            // k = kb+0
            hx = (ull)__double_as_longlong(c0v.x); hy = (ull)__double_as_longlong(c0v.y);
            #pragma unroll
            for (int i = 0; i < 4; ++i) {
                ulonglong2 w = wp2[i];                    // rows 2i, 2i+1  (LDS.128 bcast)
                fma2(acc[2*i  ][0], w.x, hx); fma2(acc[2*i  ][1], w.x, hy);
                fma2(acc[2*i+1][0], w.y, hx); fma2(acc[2*i+1][1], w.y, hy);
            }
            // k = kb+1
            hx = (ull)__double_as_longlong(c1v.x); hy = (ull)__double_as_longlong(c1v.y);
            #pragma unroll
            for (int i = 0; i < 4; ++i) {
                ulonglong2 w = wp2[8 + i];
                fma2(acc[2*i  ][0], w.x, hx); fma2(acc[2*i  ][1], w.x, hy);
                fma2(acc[2*i+1][0], w.y, hx); fma2(acc[2*i+1][1], w.y, hy);
            }
            // k = kb+2
            hx = (ull)__double_as_longlong(c2v.x); hy = (ull)__double_as_longlong(c2v.y);
            #pragma unroll
            for (int i = 0; i < 4; ++i) {
                ulonglong2 w = wp2[16 + i];
                fma2(acc[2*i  ][0], w.x, hx); fma2(acc[2*i  ][1], w.x, hy);
                fma2(acc[2*i+1][0], w.y, hx); fma2(acc[2*i+1][1], w.y, hy);
            }
            // k = kb+3
            hx = (ull)__double_as_longlong(c3v.x); hy = (ull)__double_as_longlong(c3v.y);
            #pragma unroll
            for (int i = 0; i < 4; ++i) {
                ulonglong2 w = wp2[24 + i];
                fma2(acc[2*i  ][0], w.x, hx); fma2(acc[2*i  ][1], w.x, hy);
                fma2(acc[2*i+1][0], w.y, hx); fma2(acc[2*i+1][1], w.y, hy);
            }
            c0v = n0v; c1v = n1v; c2v = n2v; c3v = n3v;
        }

        // prefetch input x for phase1 (hide its L2 latency behind psum stores/sync)
        float xv = inseq[t * BD + (tid & 127)];

        // partials -> SMEM: psum2[(kseg*16 + row)*32 + lane]
        #pragma unroll
        for (int r = 0; r < 8; ++r) {
            psum2[(kseg * 16 + rhalf * 8 + r) * 32 + lane] =
                make_ulonglong2(acc[r][0], acc[r][1]);
        }
        __syncthreads();
        // --- phase1: sum 8 k-segments + input/bias -> gates gsm[row*128+b] ---
        #pragma unroll
        for (int i = 0; i < 4; ++i) {
            int q = tid + i * NTH;               // q = row*128 + b
            int row = q >> 7;
            float s = psum_f[q]          + psum_f[2048 + q]
                    + psum_f[2*2048 + q] + psum_f[3*2048 + q]
                    + psum_f[4*2048 + q] + psum_f[5*2048 + q]
                    + psum_f[6*2048 + q] + psum_f[7*2048 + q];
            gsm[q] = s + xv * wih_s[row] + bias_s[row];
        }
        __syncthreads();
        // --- phase2: LSTM cell update + write h (fp32 history + fp16 copy) ---
        {
            int q = tid;                          // exactly 512 cells
            int jj = q >> 7, b = q & 127;
            float ig = sigf (gsm[( 0 + jj) * BD + b]);
            float fg = sigf (gsm[( 4 + jj) * BD + b]);
            float gg = tanhf(gsm[( 8 + jj) * BD + b]);
            float og = sigf (gsm[(12 + jj) * BD + b]);
            float c = fg * c_s[q] + ig * gg;
            float h = og * tanhf(c);
            c_s[q] = c;
            g_hist[(size_t)(t + 1) * HB + (4 * g + jj) * BD + b] = h;
            g_ench[(size_t)t * HB + (4 * g + jj) * BD + b] = __float2half(h);
        }
        grid_sync();
    }

    // ======= precompute p[t][b] = enc_t[b].linW (fp16 enc); x0; dec weights =======
    for (int idx = tid; idx < HDIM; idx += NTH) gsm[idx] = linW[idx];
    __syncthreads();
    for (int tt = 0; tt < 4; ++tt) {
        int t = g + tt * NCTA;
        int b2 = tid & 63, hf = tid >> 6;   // 8 chunks of 64 j-rows
        const __half2* ep = reinterpret_cast<const __half2*>(g_ench + (size_t)t * HB)
                            + (hf * 64) * 64 + b2;
        float2 a = make_float2(0.0f, 0.0f);
        #pragma unroll 4
        for (int j = 0; j < 64; ++j) {
            float2 hv = __half22float2(ep[j * 64]);
            float lw = gsm[hf * 64 + j];
            a.x += hv.x * lw; a.y += hv.y * lw;
        }
        red2[hf * 64 + b2] = a;
        __syncthreads();
        if (hf == 0) {
            float sx = 0.0f, sy = 0.0f;
            #pragma unroll
            for (int c = 0; c < 8; ++c) { float2 r = red2[c * 64 + b2]; sx += r.x; sy += r.y; }
            g_p[t * BD + 2 * b2]     = sx;
            g_p[t * BD + 2 * b2 + 1] = sy;
        }
        __syncthreads();
    }
    if (g == 0 && tid < BD) g_x[tid] = inseq[TENC * BD + tid];  // x0 = input_seq[-1]
    // decoder weights: Wd[lr][k] (w,w)-dup, lr = 0..3 (rows 4g..4g+3)
    for (int idx = tid; idx < 4 * HDIM; idx += NTH) {
        int lr = idx >> 9, k = idx & (HDIM - 1);
        float w = rWhh[(size_t)(4 * g + lr) * HDIM + k];
        Wd[lr * HDIM + k] = pk(w, w);
    }
    if (tid < 4) {
        int row = 4 * g + tid;
        bias_s[tid] = rbih[row] + rbhh[row];
        wih_s[tid]  = rWih[row];           // O == 1
    }
    grid_sync();

    // ======================= decoder: 32 steps =======================
    int cur = 0;
    for (int s = 0; s < PRED; ++s) {
        const int nxt = cur ^ 1;
        // --- RNN matvec (256 threads): h_new = tanh(x*rWih + rb + rWhh.h_old) ---
        if (tid < 256) {
            int jj = tid >> 6, bb = tid & 63;
            ull acc = 0ull;
            const float* hb = (s == 0) ? (g_hist + (size_t)TENC * HB) : g_h[cur];
            const ull*   wp = Wd + jj * HDIM;
            #pragma unroll 4
            for (int k = 0; k < HDIM; ++k) {
                double hv = __ldcg(reinterpret_cast<const double*>(hb + k * BD + bb * 2));
                fma2(acc, wp[k], (ull)__double_as_longlong(hv));
            }
            float2 f = upk(acc);
            float rwi = wih_s[jj], rb = bias_s[jj];
            int b0 = 2 * bb;
            float x0v = __ldcg(g_x + b0), x1v = __ldcg(g_x + b0 + 1);
            __stcg(&g_h[nxt][(4 * g + jj) * BD + b0],     tanhf(f.x + x0v * rwi + rb));
            __stcg(&g_h[nxt][(4 * g + jj) * BD + b0 + 1], tanhf(f.y + x1v * rwi + rb));
        }
        grid_sync();
        // --- scores[t][b] = enc_t[b] . h_new[b], enc fp16 (L2-resident) ---
        for (int tt = 0; tt < 4; ++tt) {
            int t = g + tt * NCTA;
            int b2 = tid & 63, hf = tid >> 6;
            const __half2* ep = reinterpret_cast<const __half2*>(g_ench + (size_t)t * HB)
                                + (hf * 64) * 64 + b2;
            const float2* hp = reinterpret_cast<const float2*>(g_h[nxt]) + (hf * 64) * 64 + b2;
            float2 a = make_float2(0.0f, 0.0f);
            #pragma unroll 4
            for (int j = 0; j < 64; ++j) {
                float2 hv = __half22float2(ep[j * 64]);
                float2 hh = __ldcg(hp + j * 64);
                a.x += hv.x * hh.x; a.y += hv.y * hh.y;
            }
            red2[hf * 64 + b2] = a;
            __syncthreads();
            if (hf == 0) {
                float sx = 0.0f, sy = 0.0f;
                #pragma unroll
                for (int c = 0; c < 8; ++c) { float2 r = red2[c * 64 + b2]; sx += r.x; sy += r.y; }
                g_sc[t * BD + 2 * b2]     = sx;
                g_sc[t * BD + 2 * b2 + 1] = sy;
            }
            __syncthreads();
        }
        grid_sync();
        // --- softmax over t + output; CTA g owns batch element b = g ---
        {
            float s1 = __ldcg(g_sc + tid * BD + g);   // tid covers all 512 t
            red[tid] = s1;
            __syncthreads();
            for (int off = 256; off > 0; off >>= 1) {
                if (tid < off) red[tid] = fmaxf(red[tid], red[tid + off]);
                __syncthreads();
            }
            float mall = red[0];
            __syncthreads();
            float e1 = expf(s1 - mall);
            float wp1 = e1 * g_p[tid * BD + g];
            red[tid] = e1;
            gsm[tid] = wp1;
            __syncthreads();
            for (int off = 256; off > 0; off >>= 1) {
                if (tid < off) { red[tid] += red[tid + off]; gsm[tid] += gsm[tid + off]; }
                __syncthreads();
            }
            if (tid == 0) {
                float o = fmaxf(0.0f, gsm[0] / red[0] + linb[0]);
                dout[s * BD + g] = o;
                __stcg(&g_x[g], o);
            }
        }
        grid_sync();
        cur = nxt;
    }
}

extern "C" void kernel_launch(void* const* d_in, const int* in_sizes, int n_in,
                              void* d_out, int out_size) {
    (void)in_sizes; (void)n_in; (void)out_size;
    cudaFuncSetAttribute(lstm_attn_kernel,
                         cudaFuncAttributeMaxDynamicSharedMemorySize, SMEM_BYTES);
    const float* inseq = (const float*)d_in[0];
    const float* h0    = (const float*)d_in[1];
    const float* c0    = (const float*)d_in[2];
    const float* Wih   = (const float*)d_in[3];
    const float* Whh   = (const float*)d_in[4];
    const float* bih   = (const float*)d_in[5];
    const float* bhh   = (const float*)d_in[6];
    const float* rWih  = (const float*)d_in[7];
    const float* rWhh  = (const float*)d_in[8];
    const float* rbih  = (const float*)d_in[9];
    const float* rbhh  = (const float*)d_in[10];
    const float* linW  = (const float*)d_in[11];
    const float* linb  = (const float*)d_in[12];
    float* dout = (float*)d_out;
    lstm_attn_kernel<<<NCTA, NTH, SMEM_BYTES>>>(
        inseq, h0, c0, Wih, Whh, bih, bhh,
        rWih, rWhh, rbih, rbhh, linW, linb, dout);
}